// round 2
// baseline (speedup 1.0000x reference)
#include <cuda_runtime.h>

// Problem constants
#define SQ   4096
#define BB   8
#define INF  1024
#define HID  1024
#define MTOT (SQ*BB)        // 32768
#define NTOT (3*HID)        // 3072
#define KTOT INF            // 1024
#define BH   (BB*HID)       // 8192
#define GSZ  (MTOT*HID)     // 33554432 elems per gate plane

// GEMM tiling
#define BM 128
#define BN 128
#define BK 16

// Scan chunking
#define TCH 32
#define NCH (SQ/TCH)        // 128

// Scratch: gate planes Z, F, G (384 MB) + chunk scan state
__device__ float g_gates[3ULL * GSZ];
__device__ float g_chA[NCH * BH];
__device__ float g_chB[NCH * BH];
__device__ float g_cin[NCH * BH];

// ---- packed f32x2 helpers (FFMA2 path: 2x fp32 FMA throughput on sm_103a) ----
__device__ __forceinline__ unsigned long long pk2(float lo, float hi) {
    unsigned long long r;
    asm("mov.b64 %0, {%1, %2};" : "=l"(r) : "f"(lo), "f"(hi));
    return r;
}
__device__ __forceinline__ void upk2(unsigned long long v, float& lo, float& hi) {
    asm("mov.b64 {%0, %1}, %2;" : "=f"(lo), "=f"(hi) : "l"(v));
}
__device__ __forceinline__ unsigned long long ffma2(unsigned long long a,
                                                    unsigned long long b,
                                                    unsigned long long c) {
    unsigned long long d;
    asm("fma.rn.f32x2 %0, %1, %2, %3;" : "=l"(d) : "l"(a), "l"(b), "l"(c));
    return d;
}

// ============================================================================
// Kernel 1: Y = X * W^T + b, fused activations, write gate planes.
// X: [MTOT, KTOT] row-major; W: [NTOT, KTOT] row-major.
// Gate is uniform per block: BN=128 divides HID=1024 → gate = blockIdx.x >> 3.
// ============================================================================
__global__ __launch_bounds__(256, 2) void gemm_act(const float* __restrict__ X,
                                                   const float* __restrict__ W,
                                                   const float* __restrict__ bias) {
    __shared__ float As[BK][BM + 4];
    __shared__ float Bs[BK][BN + 4];

    const int tid = threadIdx.x;
    const int m0 = blockIdx.y * BM;
    const int n0 = blockIdx.x * BN;
    const int ty = tid >> 4;      // 0..15 -> m sub-tile
    const int tx = tid & 15;      // 0..15 -> n sub-tile

    unsigned long long acc[8][4];
#pragma unroll
    for (int i = 0; i < 8; i++)
#pragma unroll
        for (int j = 0; j < 4; j++) acc[i][j] = 0ULL;   // {+0.f, +0.f}

    const float* Xb = X + (size_t)m0 * KTOT;
    const float* Wb = W + (size_t)n0 * KTOT;

    for (int kt = 0; kt < KTOT; kt += BK) {
        // Cooperative load: 128x16 A tile and 128x16 B tile, float4 granular.
#pragma unroll
        for (int it = 0; it < 2; it++) {
            int id  = tid + it * 256;        // 0..511
            int row = id >> 2;               // 0..127
            int kq  = (id & 3) * 4;          // 0,4,8,12
            float4 va = *(const float4*)(Xb + (size_t)row * KTOT + kt + kq);
            As[kq + 0][row] = va.x;
            As[kq + 1][row] = va.y;
            As[kq + 2][row] = va.z;
            As[kq + 3][row] = va.w;
            float4 vb = *(const float4*)(Wb + (size_t)row * KTOT + kt + kq);
            Bs[kq + 0][row] = vb.x;
            Bs[kq + 1][row] = vb.y;
            Bs[kq + 2][row] = vb.z;
            Bs[kq + 3][row] = vb.w;
        }
        __syncthreads();

#pragma unroll
        for (int k = 0; k < BK; k++) {
            float4 a0 = *(const float4*)&As[k][ty * 8];
            float4 a1 = *(const float4*)&As[k][ty * 8 + 4];
            float4 b0 = *(const float4*)&Bs[k][tx * 8];
            float4 b1 = *(const float4*)&Bs[k][tx * 8 + 4];
            unsigned long long bp[4] = { pk2(b0.x, b0.y), pk2(b0.z, b0.w),
                                         pk2(b1.x, b1.y), pk2(b1.z, b1.w) };
            float av[8] = { a0.x, a0.y, a0.z, a0.w, a1.x, a1.y, a1.z, a1.w };
#pragma unroll
            for (int i = 0; i < 8; i++) {
                unsigned long long ap = pk2(av[i], av[i]);
#pragma unroll
                for (int j = 0; j < 4; j++) acc[i][j] = ffma2(ap, bp[j], acc[i][j]);
            }
        }
        __syncthreads();
    }

    // Epilogue: add bias, activation (gate 0: tanh, gates 1/2: sigmoid), store.
    const int gate  = blockIdx.x >> 3;                      // 0,1,2
    const int hbase = (n0 & (HID - 1)) + tx * 8;
    float bb[8];
#pragma unroll
    for (int j = 0; j < 8; j++) bb[j] = bias[n0 + tx * 8 + j];

    float* gout = g_gates + (size_t)gate * GSZ;
#pragma unroll
    for (int i = 0; i < 8; i++) {
        int m = m0 + ty * 8 + i;
        float v[8];
#pragma unroll
        for (int j = 0; j < 4; j++) upk2(acc[i][j], v[2 * j], v[2 * j + 1]);
#pragma unroll
        for (int j = 0; j < 8; j++) {
            float y = v[j] + bb[j];
            if (gate == 0) {
                // tanh(y) = 2*sigmoid(2y) - 1
                float sg = 1.f / (1.f + __expf(-2.f * y));
                v[j] = 2.f * sg - 1.f;
            } else {
                v[j] = 1.f / (1.f + __expf(-y));
            }
        }
        float4* dst = (float4*)(gout + (size_t)m * HID + hbase);
        dst[0] = make_float4(v[0], v[1], v[2], v[3]);
        dst[1] = make_float4(v[4], v[5], v[6], v[7]);
    }
}

// ============================================================================
// Scan phase A: per-chunk affine composition. c_out = Bv + A * c_in.
// 128 chunks x 8192 channels = 1M threads -> full HBM bandwidth.
// ============================================================================
__global__ __launch_bounds__(256) void scanA() {
    const int j  = blockIdx.x * 256 + threadIdx.x;   // channel 0..8191
    const int ch = blockIdx.y;                        // chunk 0..127
    const float* Zp = g_gates;
    const float* Fp = g_gates + (size_t)GSZ;

    float A = 1.f, Bv = 0.f;
    size_t base = (size_t)ch * TCH * BH + j;
#pragma unroll 8
    for (int s = 0; s < TCH; s++) {
        size_t idx = base + (size_t)s * BH;
        float f = Fp[idx];
        float z = Zp[idx];
        float omf = 1.f - f;
        A  = A * omf;
        Bv = f * z + omf * Bv;
    }
    g_chA[ch * BH + j] = A;
    g_chB[ch * BH + j] = Bv;
}

// ============================================================================
// Scan phase B: sequential scan over 128 chunk states (8192 threads, cheap).
// Records the incoming carry for each chunk; writes C_last.
// ============================================================================
__global__ __launch_bounds__(256) void scanB(const float* __restrict__ hidden,
                                             float* __restrict__ c_last) {
    const int j = blockIdx.x * 256 + threadIdx.x;    // 0..8191
    float c = hidden[j];
#pragma unroll 4
    for (int i = 0; i < NCH; i++) {
        g_cin[i * BH + j] = c;
        c = g_chB[i * BH + j] + g_chA[i * BH + j] * c;
    }
    c_last[j] = c;
}

// ============================================================================
// Scan phase C: re-scan each chunk with the correct carry; write C and H.
// ============================================================================
__global__ __launch_bounds__(256) void scanC(float* __restrict__ Hout,
                                             float* __restrict__ Cout) {
    const int j  = blockIdx.x * 256 + threadIdx.x;
    const int ch = blockIdx.y;
    const float* Zp = g_gates;
    const float* Fp = g_gates + (size_t)GSZ;
    const float* Gp = g_gates + 2ULL * GSZ;

    float c = g_cin[ch * BH + j];
    size_t base = (size_t)ch * TCH * BH + j;
#pragma unroll 4
    for (int s = 0; s < TCH; s++) {
        size_t idx = base + (size_t)s * BH;
        float f = Fp[idx];
        float z = Zp[idx];
        float g = Gp[idx];
        c = f * z + (1.f - f) * c;
        Cout[idx] = c;
        Hout[idx] = g * c;
    }
}

// ============================================================================
// Launch: GEMM+act -> scanA -> scanB -> scanC (default stream, graph-capturable)
// Inputs: d_in[0]=X [4096,8,1024], d_in[1]=hidden [8,1024],
//         d_in[2]=W [3072,1024], d_in[3]=b [3072]
// Output: H [4096,8,1024] | C_last [1,8,1024] | C [4096,8,1024]
// ============================================================================
extern "C" void kernel_launch(void* const* d_in, const int* in_sizes, int n_in,
                              void* d_out, int out_size) {
    const float* X      = (const float*)d_in[0];
    const float* hidden = (const float*)d_in[1];
    const float* W      = (const float*)d_in[2];
    const float* bias   = (const float*)d_in[3];

    float* out   = (float*)d_out;
    float* Hout  = out;
    float* Clast = out + (size_t)GSZ;
    float* Cout  = out + (size_t)GSZ + BH;

    dim3 gg(NTOT / BN, MTOT / BM);     // (24, 256)
    gemm_act<<<gg, 256>>>(X, W, bias);
    scanA<<<dim3(BH / 256, NCH), 256>>>();
    scanB<<<BH / 256, 256>>>(hidden, Clast);
    scanC<<<dim3(BH / 256, NCH), 256>>>(Hout, Cout);
}

// round 4
// speedup vs baseline: 2.9264x; 2.9264x over previous
#include <cuda_runtime.h>
#include <cstdint>

// ---------------- problem constants ----------------
#define SQ   4096
#define BB   8
#define HID  1024
#define KTOT 1024
#define MTOT (SQ*BB)          // 32768
#define NTOT (3*HID)          // 3072
#define BH   (BB*HID)         // 8192
#define GSZ  ((size_t)MTOT*HID)

// ---------------- GEMM tiling ----------------
#define BM   128
#define BN   128
#define BK   32
#define NCHK (KTOT/BK)        // 32
// smem: padded stride 36 floats -> conflict-free fragment loads
#define STRD 36
#define A_BYTES (BM*STRD*4)   // 18432
#define B_BYTES (BN*STRD*4)   // 18432
#define STG_BYTES (A_BYTES + B_BYTES)       // 36864
#define SMEM_TOTAL (2*STG_BYTES)            // 73728

// ---------------- scan chunking ----------------
#define TCH 32
#define NCH (SQ/TCH)          // 128

// ---------------- scratch ----------------
__device__ float g_gates[3*GSZ];     // Z, F, G planes (activated)
__device__ float g_chA[NCH*BH];
__device__ float g_chB[NCH*BH];
__device__ float g_cin[NCH*BH];

// ---------------- PTX helpers ----------------
__device__ __forceinline__ uint32_t smem_u32(const void* p) {
    uint32_t a;
    asm("{ .reg .u64 t; cvta.to.shared.u64 t, %1; cvt.u32.u64 %0, t; }" : "=r"(a) : "l"(p));
    return a;
}
#define CP16(dst, src) \
    asm volatile("cp.async.cg.shared.global [%0], [%1], 16;" :: "r"(dst), "l"(src))

__device__ __forceinline__ uint32_t f2tf32(float x) {
    uint32_t u;
    asm("cvt.rna.tf32.f32 %0, %1;" : "=r"(u) : "f"(x));
    return u;
}

__device__ __forceinline__ void mma_tf32(float* d, const uint32_t* a, const uint32_t* b) {
    asm volatile(
        "mma.sync.aligned.m16n8k8.row.col.f32.tf32.tf32.f32 "
        "{%0,%1,%2,%3}, {%4,%5,%6,%7}, {%8,%9}, {%0,%1,%2,%3};"
        : "+f"(d[0]), "+f"(d[1]), "+f"(d[2]), "+f"(d[3])
        : "r"(a[0]), "r"(a[1]), "r"(a[2]), "r"(a[3]), "r"(b[0]), "r"(b[1]));
}

// ============================================================================
// tf32 mma.sync GEMM + fused activations.
// X: [MTOT, K] row-major; W: [NTOT, K] row-major; Y = X * W^T + b.
// CTA tile 128x128, 8 warps in 4(m) x 2(n), warp tile 32x64.
// ============================================================================
__global__ __launch_bounds__(256, 2) void gemm_mma(const float* __restrict__ X,
                                                   const float* __restrict__ W,
                                                   const float* __restrict__ bias) {
    extern __shared__ float smem[];
    const uint32_t sb = smem_u32(smem);
    const int tid = threadIdx.x;
    const int wid = tid >> 5;
    const int lid = tid & 31;
    const int m0 = blockIdx.y * BM;
    const int n0 = blockIdx.x * BN;

    const int warp_m = (wid & 3) * 32;     // 0,32,64,96
    const int warp_n = (wid >> 2) * 64;    // 0,64

    const float* Xb = X + (size_t)m0 * KTOT;
    const float* Wb = W + (size_t)n0 * KTOT;

    float acc[2][8][4];
#pragma unroll
    for (int mf = 0; mf < 2; mf++)
#pragma unroll
        for (int nf = 0; nf < 8; nf++)
#pragma unroll
            for (int q = 0; q < 4; q++) acc[mf][nf][q] = 0.f;

    // cooperative load of K-chunk c into stage s
    auto load_chunk = [&](int c, int s) {
        const uint32_t abase = sb + s * STG_BYTES;
        const uint32_t bbase = abase + A_BYTES;
        const int kc = c * BK;
#pragma unroll
        for (int p = 0; p < 4; p++) {
            int seg = tid + p * 256;           // 0..1023
            int row = seg >> 3, ks = seg & 7;  // row 0..127, 8 x 16B per row
            CP16(abase + row * (STRD * 4) + ks * 16,
                 Xb + (size_t)row * KTOT + kc + ks * 4);
        }
#pragma unroll
        for (int p = 0; p < 4; p++) {
            int seg = tid + p * 256;
            int row = seg >> 3, ks = seg & 7;
            CP16(bbase + row * (STRD * 4) + ks * 16,
                 Wb + (size_t)row * KTOT + kc + ks * 4);
        }
        asm volatile("cp.async.commit_group;" ::: "memory");
    };

    load_chunk(0, 0);
    load_chunk(1, 1);

    const int lr = lid >> 2;     // 0..7
    const int lc = lid & 3;      // 0..3

    for (int i = 0; i < NCHK; i++) {
        const int s = i & 1;
        if (i < NCHK - 2) asm volatile("cp.async.wait_group 1;" ::: "memory");
        else              asm volatile("cp.async.wait_group 0;" ::: "memory");
        __syncthreads();

        const float* As = smem + s * (STG_BYTES / 4);
        const float* Bs = As + (A_BYTES / 4);

#pragma unroll
        for (int k8 = 0; k8 < 4; k8++) {
            const int kk = k8 * 8;
            uint32_t af[2][4];
#pragma unroll
            for (int mf = 0; mf < 2; mf++) {
                const float* ap = As + (warp_m + mf * 16 + lr) * STRD + kk + lc;
                af[mf][0] = f2tf32(ap[0]);
                af[mf][1] = f2tf32(ap[8 * STRD]);
                af[mf][2] = f2tf32(ap[4]);
                af[mf][3] = f2tf32(ap[8 * STRD + 4]);
            }
            uint32_t bf[8][2];
#pragma unroll
            for (int nf = 0; nf < 8; nf++) {
                const float* bp = Bs + (warp_n + nf * 8 + lr) * STRD + kk + lc;
                bf[nf][0] = f2tf32(bp[0]);
                bf[nf][1] = f2tf32(bp[4]);
            }
#pragma unroll
            for (int mf = 0; mf < 2; mf++)
#pragma unroll
                for (int nf = 0; nf < 8; nf++)
                    mma_tf32(acc[mf][nf], af[mf], bf[nf]);
        }
        __syncthreads();
        if (i + 2 < NCHK) load_chunk(i + 2, s);
    }

    // ---- epilogue: bias + activation, write gate plane ----
    const int gate  = blockIdx.x >> 3;                 // 8 blocks of 128 per gate
    const int hcol0 = (blockIdx.x & 7) * BN;
    float* gout = g_gates + (size_t)gate * GSZ;

#pragma unroll
    for (int mf = 0; mf < 2; mf++) {
#pragma unroll
        for (int nf = 0; nf < 8; nf++) {
            const int ncol = warp_n + nf * 8 + 2 * lc;          // within tile
            const float b0 = bias[n0 + ncol];
            const float b1 = bias[n0 + ncol + 1];
#pragma unroll
            for (int half = 0; half < 2; half++) {
                const int m = m0 + warp_m + mf * 16 + lr + half * 8;
                float y0 = acc[mf][nf][2 * half + 0] + b0;
                float y1 = acc[mf][nf][2 * half + 1] + b1;
                float v0, v1;
                if (gate == 0) {
                    v0 = 2.f / (1.f + __expf(-2.f * y0)) - 1.f;  // tanh
                    v1 = 2.f / (1.f + __expf(-2.f * y1)) - 1.f;
                } else {
                    v0 = 1.f / (1.f + __expf(-y0));              // sigmoid
                    v1 = 1.f / (1.f + __expf(-y1));
                }
                *(float2*)(gout + (size_t)m * HID + hcol0 + ncol) = make_float2(v0, v1);
            }
        }
    }
}

// ============================================================================
// Scan phase A: per-chunk affine composition.
// ============================================================================
__global__ __launch_bounds__(256) void scanA() {
    const int j  = blockIdx.x * 256 + threadIdx.x;
    const int ch = blockIdx.y;
    const float* Zp = g_gates;
    const float* Fp = g_gates + GSZ;

    float A = 1.f, Bv = 0.f;
    size_t base = (size_t)ch * TCH * BH + j;
#pragma unroll 8
    for (int s = 0; s < TCH; s++) {
        size_t idx = base + (size_t)s * BH;
        float f = Fp[idx], z = Zp[idx];
        float omf = 1.f - f;
        A  = A * omf;
        Bv = f * z + omf * Bv;
    }
    g_chA[ch * BH + j] = A;
    g_chB[ch * BH + j] = Bv;
}

// ============================================================================
// Scan phase B: sequential over 128 chunk states; records per-chunk carry.
// ============================================================================
__global__ __launch_bounds__(256) void scanB(const float* __restrict__ hidden,
                                             float* __restrict__ c_last) {
    const int j = blockIdx.x * 256 + threadIdx.x;
    float c = hidden[j];
#pragma unroll 4
    for (int i = 0; i < NCH; i++) {
        g_cin[i * BH + j] = c;
        c = g_chB[i * BH + j] + g_chA[i * BH + j] * c;
    }
    c_last[j] = c;
}

// ============================================================================
// Scan phase C: re-scan chunks with correct carries; write C and H.
// ============================================================================
__global__ __launch_bounds__(256) void scanC(float* __restrict__ Hout,
                                             float* __restrict__ Cout) {
    const int j  = blockIdx.x * 256 + threadIdx.x;
    const int ch = blockIdx.y;
    const float* Zp = g_gates;
    const float* Fp = g_gates + GSZ;
    const float* Gp = g_gates + 2 * GSZ;

    float c = g_cin[ch * BH + j];
    size_t base = (size_t)ch * TCH * BH + j;
#pragma unroll 4
    for (int s = 0; s < TCH; s++) {
        size_t idx = base + (size_t)s * BH;
        float f = Fp[idx], z = Zp[idx], g = Gp[idx];
        c = f * z + (1.f - f) * c;
        Cout[idx] = c;
        Hout[idx] = g * c;
    }
}

// ============================================================================
// Launch
// ============================================================================
extern "C" void kernel_launch(void* const* d_in, const int* in_sizes, int n_in,
                              void* d_out, int out_size) {
    const float* X      = (const float*)d_in[0];
    const float* hidden = (const float*)d_in[1];
    const float* W      = (const float*)d_in[2];
    const float* bias   = (const float*)d_in[3];

    float* out   = (float*)d_out;
    float* Hout  = out;
    float* Clast = out + GSZ;
    float* Cout  = out + GSZ + BH;

    cudaFuncSetAttribute(gemm_mma, cudaFuncAttributeMaxDynamicSharedMemorySize, SMEM_TOTAL);

    gemm_mma<<<dim3(NTOT / BN, MTOT / BM), 256, SMEM_TOTAL>>>(X, W, bias);
    scanA<<<dim3(BH / 256, NCH), 256>>>();
    scanB<<<BH / 256, 256>>>(hidden, Clast);
    scanC<<<dim3(BH / 256, NCH), 256>>>(Hout, Cout);
}

// round 5
// speedup vs baseline: 3.2228x; 1.1013x over previous
#include <cuda_runtime.h>
#include <cstdint>

// ---------------- problem constants ----------------
#define SQ   4096
#define BB   8
#define HID  1024
#define KTOT 1024
#define MTOT (SQ*BB)          // 32768
#define NTOT (3*HID)          // 3072
#define BH   (BB*HID)         // 8192
#define GSZ  ((size_t)MTOT*HID)

// ---------------- GEMM tiling ----------------
#define BM   128
#define BN   128
#define BK   32
#define NCHK (KTOT/BK)        // 32
#define STRD 36               // padded row stride (floats): conflict-free ldmatrix
#define A_BYTES (BM*STRD*4)   // 18432
#define B_BYTES (BN*STRD*4)   // 18432
#define STG_BYTES (A_BYTES + B_BYTES)   // 36864
#define SMEM_TOTAL (2*STG_BYTES)        // 73728

// ---------------- scan chunking ----------------
#define TCH 32
#define NCH (SQ/TCH)          // 128

// ---------------- scratch ----------------
__device__ float    g_gates[3*GSZ];          // Z, F, G planes (activated)
__device__ uint32_t g_xt[(size_t)MTOT*KTOT]; // X as tf32 bits
__device__ uint32_t g_wt[(size_t)NTOT*KTOT]; // W as tf32 bits
__device__ float    g_chA[NCH*BH];
__device__ float    g_chB[NCH*BH];
__device__ float    g_cin[NCH*BH];

// ---------------- PTX helpers ----------------
__device__ __forceinline__ uint32_t smem_u32(const void* p) {
    uint32_t a;
    asm("{ .reg .u64 t; cvta.to.shared.u64 t, %1; cvt.u32.u64 %0, t; }" : "=r"(a) : "l"(p));
    return a;
}
#define CP16(dst, src) \
    asm volatile("cp.async.cg.shared.global [%0], [%1], 16;" :: "r"(dst), "l"(src))

__device__ __forceinline__ uint32_t f2tf32(float x) {
    uint32_t u;
    asm("cvt.rna.tf32.f32 %0, %1;" : "=r"(u) : "f"(x));
    return u;
}
__device__ __forceinline__ void ldsm4(uint32_t* r, uint32_t addr) {
    asm volatile("ldmatrix.sync.aligned.m8n8.x4.shared.b16 {%0,%1,%2,%3}, [%4];"
                 : "=r"(r[0]), "=r"(r[1]), "=r"(r[2]), "=r"(r[3]) : "r"(addr));
}
__device__ __forceinline__ void mma_tf32(float* d, const uint32_t* a, const uint32_t* b) {
    asm volatile(
        "mma.sync.aligned.m16n8k8.row.col.f32.tf32.tf32.f32 "
        "{%0,%1,%2,%3}, {%4,%5,%6,%7}, {%8,%9}, {%0,%1,%2,%3};"
        : "+f"(d[0]), "+f"(d[1]), "+f"(d[2]), "+f"(d[3])
        : "r"(a[0]), "r"(a[1]), "r"(a[2]), "r"(a[3]), "r"(b[0]), "r"(b[1]));
}

// ============================================================================
// Pre-convert fp32 -> tf32 bit patterns (RNA), float4 granularity.
// ============================================================================
__global__ __launch_bounds__(256) void conv_tf32(const float* __restrict__ src,
                                                 uint32_t* __restrict__ dst,
                                                 int n4) {
    int i = blockIdx.x * 256 + threadIdx.x;
    if (i >= n4) return;
    float4 v = ((const float4*)src)[i];
    uint4 o;
    o.x = f2tf32(v.x); o.y = f2tf32(v.y); o.z = f2tf32(v.z); o.w = f2tf32(v.w);
    ((uint4*)dst)[i] = o;
}

// ============================================================================
// tf32 mma.sync GEMM (pre-converted inputs) + fused activations.
// CTA tile 128x128, 8 warps 4(m) x 2(n), warp tile 32x64, ldmatrix fragments.
// ============================================================================
__global__ __launch_bounds__(256, 2) void gemm_mma(const float* __restrict__ bias) {
    extern __shared__ uint32_t smem[];
    const uint32_t sb = smem_u32(smem);
    const int tid = threadIdx.x;
    const int wid = tid >> 5;
    const int lid = tid & 31;
    const int m0 = blockIdx.y * BM;
    const int n0 = blockIdx.x * BN;

    const int warp_m = (wid & 3) * 32;     // 0,32,64,96
    const int warp_n = (wid >> 2) * 64;    // 0,64

    const uint32_t* Xb = g_xt + (size_t)m0 * KTOT;
    const uint32_t* Wb = g_wt + (size_t)n0 * KTOT;

    float acc[2][8][4];
#pragma unroll
    for (int mf = 0; mf < 2; mf++)
#pragma unroll
        for (int nf = 0; nf < 8; nf++)
#pragma unroll
            for (int q = 0; q < 4; q++) acc[mf][nf][q] = 0.f;

    auto load_chunk = [&](int c, int s) {
        const uint32_t abase = sb + s * STG_BYTES;
        const uint32_t bbase = abase + A_BYTES;
        const int kc = c * BK;
#pragma unroll
        for (int p = 0; p < 4; p++) {
            int seg = tid + p * 256;
            int row = seg >> 3, ks = seg & 7;
            CP16(abase + row * (STRD * 4) + ks * 16,
                 Xb + (size_t)row * KTOT + kc + ks * 4);
        }
#pragma unroll
        for (int p = 0; p < 4; p++) {
            int seg = tid + p * 256;
            int row = seg >> 3, ks = seg & 7;
            CP16(bbase + row * (STRD * 4) + ks * 16,
                 Wb + (size_t)row * KTOT + kc + ks * 4);
        }
        asm volatile("cp.async.commit_group;" ::: "memory");
    };

    load_chunk(0, 0);
    load_chunk(1, 1);

    // ldmatrix per-thread source rows
    const int a_row = (lid & 7) + 8 * ((lid >> 3) & 1);   // row within 16
    const int a_kq  = 4 * (lid >> 4);                      // 0 or 4
    const int b_row = (lid & 7) + 8 * (lid >> 4);          // n row within 16 (2 frags)
    const int b_kq  = 4 * ((lid >> 3) & 1);                // 0 or 4

    for (int i = 0; i < NCHK; i++) {
        const int s = i & 1;
        if (i < NCHK - 2) asm volatile("cp.async.wait_group 1;" ::: "memory");
        else              asm volatile("cp.async.wait_group 0;" ::: "memory");
        __syncthreads();

        const uint32_t abase = sb + s * STG_BYTES;
        const uint32_t bbase = abase + A_BYTES;
        const uint32_t aaddr = abase + (warp_m + a_row) * (STRD * 4) + a_kq * 4;
        const uint32_t baddr = bbase + (warp_n + b_row) * (STRD * 4) + b_kq * 4;

#pragma unroll
        for (int k8 = 0; k8 < 4; k8++) {
            const int kk = k8 * 32;            // byte offset of k8*8 floats
            uint32_t af[2][4];
            ldsm4(af[0], aaddr + kk);
            ldsm4(af[1], aaddr + 16 * (STRD * 4) + kk);
            uint32_t bf[8][2];
#pragma unroll
            for (int np = 0; np < 4; np++)
                ldsm4(bf[2 * np], baddr + np * 16 * (STRD * 4) + kk);
#pragma unroll
            for (int mf = 0; mf < 2; mf++)
#pragma unroll
                for (int nf = 0; nf < 8; nf++)
                    mma_tf32(acc[mf][nf], af[mf], bf[nf]);
        }
        __syncthreads();
        if (i + 2 < NCHK) load_chunk(i + 2, s);
    }

    // ---- epilogue: bias + activation, write gate plane ----
    const int lr = lid >> 2;
    const int lc = lid & 3;
    const int gate  = blockIdx.x >> 3;
    const int hcol0 = (blockIdx.x & 7) * BN;
    float* gout = g_gates + (size_t)gate * GSZ;

#pragma unroll
    for (int mf = 0; mf < 2; mf++) {
#pragma unroll
        for (int nf = 0; nf < 8; nf++) {
            const int ncol = warp_n + nf * 8 + 2 * lc;
            const float b0 = __ldg(&bias[n0 + ncol]);
            const float b1 = __ldg(&bias[n0 + ncol + 1]);
#pragma unroll
            for (int half = 0; half < 2; half++) {
                const int m = m0 + warp_m + mf * 16 + lr + half * 8;
                float y0 = acc[mf][nf][2 * half + 0] + b0;
                float y1 = acc[mf][nf][2 * half + 1] + b1;
                float v0, v1;
                if (gate == 0) {
                    v0 = 2.f / (1.f + __expf(-2.f * y0)) - 1.f;  // tanh
                    v1 = 2.f / (1.f + __expf(-2.f * y1)) - 1.f;
                } else {
                    v0 = 1.f / (1.f + __expf(-y0));              // sigmoid
                    v1 = 1.f / (1.f + __expf(-y1));
                }
                *(float2*)(gout + (size_t)m * HID + hcol0 + ncol) = make_float2(v0, v1);
            }
        }
    }
}

// ============================================================================
// Scan phase A: per-chunk affine composition.
// ============================================================================
__global__ __launch_bounds__(256) void scanA() {
    const int j  = blockIdx.x * 256 + threadIdx.x;
    const int ch = blockIdx.y;
    const float* Zp = g_gates;
    const float* Fp = g_gates + GSZ;

    float A = 1.f, Bv = 0.f;
    size_t base = (size_t)ch * TCH * BH + j;
#pragma unroll 8
    for (int s = 0; s < TCH; s++) {
        size_t idx = base + (size_t)s * BH;
        float f = Fp[idx], z = Zp[idx];
        float omf = 1.f - f;
        A  = A * omf;
        Bv = f * z + omf * Bv;
    }
    g_chA[ch * BH + j] = A;
    g_chB[ch * BH + j] = Bv;
}

// ============================================================================
// Scan phase B: sequential over 128 chunk states; records per-chunk carry.
// ============================================================================
__global__ __launch_bounds__(256) void scanB(const float* __restrict__ hidden,
                                             float* __restrict__ c_last) {
    const int j = blockIdx.x * 256 + threadIdx.x;
    float c = hidden[j];
#pragma unroll 4
    for (int i = 0; i < NCH; i++) {
        g_cin[i * BH + j] = c;
        c = g_chB[i * BH + j] + g_chA[i * BH + j] * c;
    }
    c_last[j] = c;
}

// ============================================================================
// Scan phase C: re-scan chunks with correct carries; write C and H.
// ============================================================================
__global__ __launch_bounds__(256) void scanC(float* __restrict__ Hout,
                                             float* __restrict__ Cout) {
    const int j  = blockIdx.x * 256 + threadIdx.x;
    const int ch = blockIdx.y;
    const float* Zp = g_gates;
    const float* Fp = g_gates + GSZ;
    const float* Gp = g_gates + 2 * GSZ;

    float c = g_cin[ch * BH + j];
    size_t base = (size_t)ch * TCH * BH + j;
#pragma unroll 4
    for (int s = 0; s < TCH; s++) {
        size_t idx = base + (size_t)s * BH;
        float f = Fp[idx], z = Zp[idx], g = Gp[idx];
        c = f * z + (1.f - f) * c;
        Cout[idx] = c;
        Hout[idx] = g * c;
    }
}

// ============================================================================
// Launch
// ============================================================================
extern "C" void kernel_launch(void* const* d_in, const int* in_sizes, int n_in,
                              void* d_out, int out_size) {
    const float* X      = (const float*)d_in[0];
    const float* hidden = (const float*)d_in[1];
    const float* W      = (const float*)d_in[2];
    const float* bias   = (const float*)d_in[3];

    float* out   = (float*)d_out;
    float* Hout  = out;
    float* Clast = out + GSZ;
    float* Cout  = out + GSZ + BH;

    uint32_t* xt; uint32_t* wt;
    cudaGetSymbolAddress((void**)&xt, g_xt);
    cudaGetSymbolAddress((void**)&wt, g_wt);

    cudaFuncSetAttribute(gemm_mma, cudaFuncAttributeMaxDynamicSharedMemorySize, SMEM_TOTAL);

    const int xn4 = (int)((size_t)MTOT * KTOT / 4);
    const int wn4 = (int)((size_t)NTOT * KTOT / 4);
    conv_tf32<<<(xn4 + 255) / 256, 256>>>(X, xt, xn4);
    conv_tf32<<<(wn4 + 255) / 256, 256>>>(W, wt, wn4);
    gemm_mma<<<dim3(NTOT / BN, MTOT / BM), 256, SMEM_TOTAL>>>(bias);
    scanA<<<dim3(BH / 256, NCH), 256>>>();
    scanB<<<BH / 256, 256>>>(hidden, Clast);
    scanC<<<dim3(BH / 256, NCH), 256>>>(Hout, Cout);
}